// round 1
// baseline (speedup 1.0000x reference)
#include <cuda_runtime.h>
#include <cuda_bf16.h>
#include <math.h>

// Problem constants
#define Bsz 1024
#define Lsz 256
#define Esz 256
#define Csz 2000
#define Vsz 200000
#define TEMP_INV 10.0f
#define MIN_NEG 10

// Scratch (allocation-free rule: __device__ globals)
__device__ float g_pooled[Bsz * Esz];
__device__ float g_norm[Bsz * Esz];
__device__ float g_sim[Bsz * Bsz];
__device__ float g_ce[Bsz];
__device__ float g_con[Bsz];
__device__ float g_hp[Bsz];
__device__ int   g_negidx[Bsz];

// ---------------------------------------------------------------------------
// 1) Masked mean pooling + L2 normalize.
//    One block per row b; thread t owns embedding column t.
//    Token ids staged in smem; each loop iter reads one coalesced 1KB table row.
// ---------------------------------------------------------------------------
__global__ void pool_kernel(const int* __restrict__ ids,
                            const float* __restrict__ emb) {
    int b = blockIdx.x;
    int t = threadIdx.x;
    __shared__ int sid[Lsz];
    sid[t] = ids[b * Lsz + t];
    __syncthreads();

    float acc = 0.f;
    int cnt = 0;
    #pragma unroll 8
    for (int l = 0; l < Lsz; l++) {
        int id = sid[l];
        if (id > 1) {  // mask: id != 0 (UNK) && id != 1 (PAD)
            acc += emb[(size_t)id * Esz + t];
            cnt++;
        }
    }
    float p = acc / (float)cnt;

    __shared__ float sh[Esz];
    sh[t] = p * p;
    __syncthreads();
    for (int s = 128; s > 0; s >>= 1) {
        if (t < s) sh[t] += sh[t + s];
        __syncthreads();
    }
    float inv = 1.0f / sqrtf(sh[0]);
    g_pooled[b * Esz + t] = p;
    g_norm[b * Esz + t]   = p * inv;
}

// ---------------------------------------------------------------------------
// 2) logits = pooled @ fc_w + fc_b   [1024,256]x[256,2000]
//    64x64 tile, 16x16 threads, 4x4 per thread, TK=16.
// ---------------------------------------------------------------------------
__global__ void gemm_logits_kernel(const float* __restrict__ W,
                                   const float* __restrict__ bias,
                                   float* __restrict__ out) {
    __shared__ float As[16][64];
    __shared__ float Bs[16][64];
    int t = threadIdx.x;
    int tx = t & 15, ty = t >> 4;
    int n0 = blockIdx.x * 64, m0 = blockIdx.y * 64;
    float acc[4][4] = {};

    for (int kk = 0; kk < Esz; kk += 16) {
        #pragma unroll
        for (int i = 0; i < 4; i++) {
            int idx = t + i * 256;
            int m = idx >> 4, k = idx & 15;
            As[k][m] = g_pooled[(m0 + m) * Esz + kk + k];
        }
        #pragma unroll
        for (int i = 0; i < 4; i++) {
            int idx = t + i * 256;
            int k = idx >> 6, n = idx & 63;
            int col = n0 + n;
            Bs[k][n] = (col < Csz) ? W[(kk + k) * Csz + col] : 0.f;
        }
        __syncthreads();
        #pragma unroll
        for (int k = 0; k < 16; k++) {
            float a[4], bv[4];
            #pragma unroll
            for (int i = 0; i < 4; i++) a[i] = As[k][ty * 4 + i];
            #pragma unroll
            for (int j = 0; j < 4; j++) bv[j] = Bs[k][tx * 4 + j];
            #pragma unroll
            for (int i = 0; i < 4; i++)
                #pragma unroll
                for (int j = 0; j < 4; j++)
                    acc[i][j] += a[i] * bv[j];
        }
        __syncthreads();
    }
    #pragma unroll
    for (int i = 0; i < 4; i++) {
        int row = m0 + ty * 4 + i;
        #pragma unroll
        for (int j = 0; j < 4; j++) {
            int col = n0 + tx * 4 + j;
            if (col < Csz) out[(size_t)row * Csz + col] = acc[i][j] + bias[col];
        }
    }
}

// ---------------------------------------------------------------------------
// 3) sim = (norm @ norm^T) / TEMP   [1024,1024]
// ---------------------------------------------------------------------------
__global__ void gemm_sim_kernel() {
    __shared__ float As[16][64];
    __shared__ float Bs[16][65];  // pad to soften transposed-store conflicts
    int t = threadIdx.x;
    int tx = t & 15, ty = t >> 4;
    int n0 = blockIdx.x * 64, m0 = blockIdx.y * 64;
    float acc[4][4] = {};

    for (int kk = 0; kk < Esz; kk += 16) {
        #pragma unroll
        for (int i = 0; i < 4; i++) {
            int idx = t + i * 256;
            int m = idx >> 4, k = idx & 15;
            As[k][m] = g_norm[(m0 + m) * Esz + kk + k];
        }
        #pragma unroll
        for (int i = 0; i < 4; i++) {
            int idx = t + i * 256;
            int n = idx >> 4, k = idx & 15;
            Bs[k][n] = g_norm[(n0 + n) * Esz + kk + k];
        }
        __syncthreads();
        #pragma unroll
        for (int k = 0; k < 16; k++) {
            float a[4], bv[4];
            #pragma unroll
            for (int i = 0; i < 4; i++) a[i] = As[k][ty * 4 + i];
            #pragma unroll
            for (int j = 0; j < 4; j++) bv[j] = Bs[k][tx * 4 + j];
            #pragma unroll
            for (int i = 0; i < 4; i++)
                #pragma unroll
                for (int j = 0; j < 4; j++)
                    acc[i][j] += a[i] * bv[j];
        }
        __syncthreads();
    }
    #pragma unroll
    for (int i = 0; i < 4; i++) {
        int row = m0 + ty * 4 + i;
        #pragma unroll
        for (int j = 0; j < 4; j++) {
            int col = n0 + tx * 4 + j;
            g_sim[row * Bsz + col] = acc[i][j] * TEMP_INV;
        }
    }
}

// ---------------------------------------------------------------------------
// 4) Cross-entropy per row (stable log-softmax over C=2000)
// ---------------------------------------------------------------------------
__global__ void ce_kernel(const float* __restrict__ logits,
                          const int* __restrict__ labels) {
    int b = blockIdx.x;
    int t = threadIdx.x;
    const float* row = logits + (size_t)b * Csz;
    __shared__ float sh[256];

    float m = -1e30f;
    for (int c = t; c < Csz; c += 256) m = fmaxf(m, row[c]);
    sh[t] = m;
    __syncthreads();
    for (int s = 128; s > 0; s >>= 1) {
        if (t < s) sh[t] = fmaxf(sh[t], sh[t + s]);
        __syncthreads();
    }
    float mx = sh[0];
    __syncthreads();

    float ssum = 0.f;
    for (int c = t; c < Csz; c += 256) ssum += expf(row[c] - mx);
    sh[t] = ssum;
    __syncthreads();
    for (int s = 128; s > 0; s >>= 1) {
        if (t < s) sh[t] += sh[t + s];
        __syncthreads();
    }
    if (t == 0) {
        float lse = mx + logf(sh[0]);
        g_ce[b] = -(row[labels[b]] - lse);
    }
}

// ---------------------------------------------------------------------------
// 5) Negative-mask priority selection: per row i, count 8 conditions over j,
//    pick first with count >= MIN_NEG, else 7.
// ---------------------------------------------------------------------------
__global__ void negidx_kernel(const int* __restrict__ lab,
                              const int* __restrict__ doc,
                              const int* __restrict__ dom,
                              const int* __restrict__ dgen,
                              const int* __restrict__ scr) {
    int i = blockIdx.x;
    int t = threadIdx.x;
    int li = lab[i], di = doc[i], dmi = dom[i], dgi = dgen[i], si = scr[i];

    int c[8] = {0, 0, 0, 0, 0, 0, 0, 0};
    for (int j = t; j < Bsz; j += 256) {
        if (lab[j] != li) {
            int sc = (scr[j] == si);
            int dc = (doc[j] == di);
            int dm = (dom[j] == dmi);
            int dg = (dgen[j] == dgi);
            c[0] += sc & dc;
            c[1] += sc & dm;
            c[2] += sc & dg;
            c[3] += sc;
            c[4] += dc;
            c[5] += dm;
            c[6] += dg;
            c[7] += 1;
        }
    }
    __shared__ int tot[8];
    if (t < 8) tot[t] = 0;
    __syncthreads();
    #pragma unroll
    for (int k = 0; k < 8; k++)
        if (c[k]) atomicAdd(&tot[k], c[k]);
    __syncthreads();
    if (t == 0) {
        int idx = 7;
        #pragma unroll
        for (int k = 7; k >= 0; k--)
            if (tot[k] >= MIN_NEG) idx = k;
        g_negidx[i] = idx;
    }
}

// ---------------------------------------------------------------------------
// 6) Contrastive per-row loss using selected negative condition
// ---------------------------------------------------------------------------
__global__ void conloss_kernel(const int* __restrict__ lab,
                               const int* __restrict__ doc,
                               const int* __restrict__ dom,
                               const int* __restrict__ dgen,
                               const int* __restrict__ scr) {
    int i = blockIdx.x;
    int t = threadIdx.x;
    int idx = g_negidx[i];
    int li = lab[i], di = doc[i], dmi = dom[i], dgi = dgen[i], si = scr[i];

    float ps = 0.f, ns = 0.f;
    for (int j = t; j < Bsz; j += 256) {
        float e = expf(g_sim[i * Bsz + j]);
        int lj = lab[j];
        if (lj == li) {
            if (j != i) ps += e;
        } else {
            bool neg;
            bool sc = (scr[j] == si);
            bool dc = (doc[j] == di);
            bool dm = (dom[j] == dmi);
            bool dg = (dgen[j] == dgi);
            switch (idx) {
                case 0: neg = sc && dc; break;
                case 1: neg = sc && dm; break;
                case 2: neg = sc && dg; break;
                case 3: neg = sc; break;
                case 4: neg = dc; break;
                case 5: neg = dm; break;
                case 6: neg = dg; break;
                default: neg = true; break;
            }
            if (neg) ns += e;
        }
    }
    __shared__ float shp[256];
    __shared__ float shn[256];
    shp[t] = ps;
    shn[t] = ns;
    __syncthreads();
    for (int s = 128; s > 0; s >>= 1) {
        if (t < s) { shp[t] += shp[t + s]; shn[t] += shn[t + s]; }
        __syncthreads();
    }
    if (t == 0) {
        float psum = shp[0], nsum = shn[0];
        if (psum != 0.f) {
            g_con[i] = -logf(psum / (psum + nsum));
            g_hp[i]  = 1.f;
        } else {
            g_con[i] = 0.f;
            g_hp[i]  = 0.f;
        }
    }
}

// ---------------------------------------------------------------------------
// 7) Final scalar: loss = mean(ce) + sum(con)/cnt (if cnt>0)
// ---------------------------------------------------------------------------
__global__ void final_kernel(float* __restrict__ out) {
    int t = threadIdx.x;  // 1024 threads
    __shared__ float s_ce[1024];
    __shared__ float s_co[1024];
    __shared__ float s_hp[1024];
    s_ce[t] = g_ce[t];
    s_co[t] = g_con[t];
    s_hp[t] = g_hp[t];
    __syncthreads();
    for (int s = 512; s > 0; s >>= 1) {
        if (t < s) {
            s_ce[t] += s_ce[t + s];
            s_co[t] += s_co[t + s];
            s_hp[t] += s_hp[t + s];
        }
        __syncthreads();
    }
    if (t == 0) {
        float ce = s_ce[0] / (float)Bsz;
        float cnt = s_hp[0];
        float con = (cnt > 0.f) ? (s_co[0] / cnt) : 0.f;
        out[0] = ce + con;
    }
}

// ---------------------------------------------------------------------------
extern "C" void kernel_launch(void* const* d_in, const int* in_sizes, int n_in,
                              void* d_out, int out_size) {
    const int*   input_ids = (const int*)d_in[0];
    const int*   labels    = (const int*)d_in[1];
    const int*   doc_ids   = (const int*)d_in[2];
    const int*   dom_ids   = (const int*)d_in[3];
    const int*   dgen_ids  = (const int*)d_in[4];
    const int*   scr_ids   = (const int*)d_in[5];
    const float* emb_table = (const float*)d_in[6];
    const float* fc_w      = (const float*)d_in[7];
    const float* fc_b      = (const float*)d_in[8];

    float* out    = (float*)d_out;
    float* logits = out + 1;  // output tuple flattened: [loss, logits(B*C)]

    pool_kernel<<<Bsz, Esz>>>(input_ids, emb_table);
    gemm_logits_kernel<<<dim3((Csz + 63) / 64, Bsz / 64), 256>>>(fc_w, fc_b, logits);
    gemm_sim_kernel<<<dim3(Bsz / 64, Bsz / 64), 256>>>();
    ce_kernel<<<Bsz, 256>>>(logits, labels);
    negidx_kernel<<<Bsz, 256>>>(labels, doc_ids, dom_ids, dgen_ids, scr_ids);
    conloss_kernel<<<Bsz, 256>>>(labels, doc_ids, dom_ids, dgen_ids, scr_ids);
    final_kernel<<<1, 1024>>>(out);
}

// round 3
// speedup vs baseline: 1.0008x; 1.0008x over previous
#include <cuda_runtime.h>
#include <math.h>

#define Bsz 1024
#define Lsz 256
#define Esz 256
#define Csz 2000
#define MIN_NEG 10

// Scratch (__device__ globals: allocation-free rule)
__device__ float g_pooled[Bsz * Esz];
__device__ float g_norm[Bsz * Esz];
__device__ float g_ce[Bsz];
__device__ float g_ps[Bsz];
__device__ float g_ns[Bsz];
__device__ int   g_negidx[Bsz];

// ---------------------------------------------------------------------------
// 1) Masked mean pooling + L2 normalize. 4 rows per block, 64 threads/row,
//    float4 (16B) per thread -> each iter is one coalesced 1KB table row.
// ---------------------------------------------------------------------------
__global__ void pool_kernel(const int* __restrict__ ids,
                            const float* __restrict__ emb) {
    int t = threadIdx.x;
    int sub = t >> 6;          // row within block (0..3)
    int lane = t & 63;         // float4 column
    int b = blockIdx.x * 4 + sub;

    __shared__ int sid[4 * 256];
    #pragma unroll
    for (int i = 0; i < 4; i++)
        sid[t + i * 256] = ids[blockIdx.x * 1024 + t + i * 256];
    __syncthreads();

    const float4* emb4 = (const float4*)emb;
    const int* myids = &sid[sub * 256];
    float4 acc = make_float4(0.f, 0.f, 0.f, 0.f);
    int cnt = 0;
    #pragma unroll 4
    for (int l = 0; l < Lsz; l++) {
        int id = myids[l];
        if (id > 1) {  // id != UNK(0) && id != PAD(1)
            float4 v = emb4[(size_t)id * 64 + lane];
            acc.x += v.x; acc.y += v.y; acc.z += v.z; acc.w += v.w;
            cnt++;
        }
    }
    float ic = 1.0f / (float)cnt;
    float4 p = make_float4(acc.x * ic, acc.y * ic, acc.z * ic, acc.w * ic);

    __shared__ float sh[256];
    sh[t] = p.x * p.x + p.y * p.y + p.z * p.z + p.w * p.w;
    __syncthreads();
    for (int s = 32; s > 0; s >>= 1) {
        if (lane < s) sh[t] += sh[t + s];
        __syncthreads();
    }
    float inv = rsqrtf(sh[sub << 6]);

    float4* P4 = (float4*)g_pooled;
    float4* N4 = (float4*)g_norm;
    P4[b * 64 + lane] = p;
    N4[b * 64 + lane] = make_float4(p.x * inv, p.y * inv, p.z * inv, p.w * inv);
}

// ---------------------------------------------------------------------------
// 2) logits = pooled @ fc_w + fc_b   [1024,256]x[256,2000]
//    BM=64, BN=128, BK=8, 256 threads, 4x8 micro-tile.
// ---------------------------------------------------------------------------
__global__ void gemm_logits_kernel(const float* __restrict__ W,
                                   const float* __restrict__ bias,
                                   float* __restrict__ out) {
    __shared__ float As[8][64];
    __shared__ float Bs[8][128];
    int t = threadIdx.x;
    int tx = t & 15, ty = t >> 4;
    int n0 = blockIdx.x * 128, m0 = blockIdx.y * 64;
    float acc[4][8] = {};
    const float4* P4 = (const float4*)g_pooled;

    for (int kk = 0; kk < Esz; kk += 8) {
        if (t < 128) {
            int arow = t >> 1, ak = (t & 1) * 4;
            float4 a = P4[(m0 + arow) * 64 + ((kk + ak) >> 2)];
            As[ak + 0][arow] = a.x; As[ak + 1][arow] = a.y;
            As[ak + 2][arow] = a.z; As[ak + 3][arow] = a.w;
        }
        {
            int bk = t >> 5, bn = (t & 31) * 4;
            int col = n0 + bn;
            float4 bv = make_float4(0.f, 0.f, 0.f, 0.f);
            if (col < Csz)  // col %4==0 and Csz%4==0 -> full float4 valid
                bv = *(const float4*)&W[(size_t)(kk + bk) * Csz + col];
            *(float4*)&Bs[bk][bn] = bv;
        }
        __syncthreads();
        #pragma unroll
        for (int k = 0; k < 8; k++) {
            float4 a  = *(const float4*)&As[k][ty * 4];
            float4 b0 = *(const float4*)&Bs[k][tx * 8];
            float4 b1 = *(const float4*)&Bs[k][tx * 8 + 4];
            float av[4] = {a.x, a.y, a.z, a.w};
            float bv[8] = {b0.x, b0.y, b0.z, b0.w, b1.x, b1.y, b1.z, b1.w};
            #pragma unroll
            for (int i = 0; i < 4; i++)
                #pragma unroll
                for (int j = 0; j < 8; j++)
                    acc[i][j] += av[i] * bv[j];
        }
        __syncthreads();
    }

    float bb[8];
    #pragma unroll
    for (int j = 0; j < 8; j++) {
        int col = n0 + tx * 8 + j;
        bb[j] = (col < Csz) ? bias[col] : 0.f;
    }
    #pragma unroll
    for (int i = 0; i < 4; i++) {
        int row = m0 + ty * 4 + i;
        #pragma unroll
        for (int j = 0; j < 8; j++) {
            int col = n0 + tx * 8 + j;
            if (col < Csz) out[(size_t)row * Csz + col] = acc[i][j] + bb[j];
        }
    }
}

// ---------------------------------------------------------------------------
// 3) Negative-condition selection per row; also zeroes g_ps/g_ns.
//    Runs strictly before sim_con_kernel in stream order, so the zeroing is
//    race-free with respect to its atomics.
// ---------------------------------------------------------------------------
__global__ void negidx_kernel(const int* __restrict__ lab,
                              const int* __restrict__ doc,
                              const int* __restrict__ dom,
                              const int* __restrict__ dgen,
                              const int* __restrict__ scr) {
    int i = blockIdx.x;
    int t = threadIdx.x;
    if (t == 0) { g_ps[i] = 0.f; g_ns[i] = 0.f; }
    int li = lab[i], di = doc[i], dmi = dom[i], dgi = dgen[i], si = scr[i];

    int c[8] = {0,0,0,0,0,0,0,0};
    for (int j = t; j < Bsz; j += 256) {
        if (lab[j] != li) {
            int sc = (scr[j] == si);
            int dc = (doc[j] == di);
            int dm = (dom[j] == dmi);
            int dg = (dgen[j] == dgi);
            c[0] += sc & dc; c[1] += sc & dm; c[2] += sc & dg; c[3] += sc;
            c[4] += dc;      c[5] += dm;      c[6] += dg;      c[7] += 1;
        }
    }
    __shared__ int tot[8];
    if (t < 8) tot[t] = 0;
    __syncthreads();
    #pragma unroll
    for (int k = 0; k < 8; k++)
        if (c[k]) atomicAdd(&tot[k], c[k]);
    __syncthreads();
    if (t == 0) {
        int idx = 7;
        #pragma unroll
        for (int k = 7; k >= 0; k--)
            if (tot[k] >= MIN_NEG) idx = k;
        g_negidx[i] = idx;
    }
}

// ---------------------------------------------------------------------------
// 4) Fused sim-GEMM + contrastive partial sums. Never materializes sim.
//    BM=64, BN=128, BK=8. Epilogue: e=exp(10*sim), classify pos/neg,
//    shuffle-reduce over cols, atomicAdd per-row ps/ns.
// ---------------------------------------------------------------------------
__global__ void sim_con_kernel(const int* __restrict__ lab,
                               const int* __restrict__ doc,
                               const int* __restrict__ dom,
                               const int* __restrict__ dgen,
                               const int* __restrict__ scr) {
    __shared__ float As[8][64];
    __shared__ float Bs[8][128];
    __shared__ int s_lm[64], s_dcm[64], s_dmm[64], s_dgm[64], s_scm[64], s_ixm[64];
    __shared__ int s_ln[128], s_dcn[128], s_dmn[128], s_dgn[128], s_scn[128];

    int t = threadIdx.x;
    int tx = t & 15, ty = t >> 4;
    int n0 = blockIdx.x * 128, m0 = blockIdx.y * 64;

    if (t < 64) {
        int i = m0 + t;
        s_lm[t] = lab[i]; s_dcm[t] = doc[i]; s_dmm[t] = dom[i];
        s_dgm[t] = dgen[i]; s_scm[t] = scr[i]; s_ixm[t] = g_negidx[i];
    }
    if (t < 128) {
        int j = n0 + t;
        s_ln[t] = lab[j]; s_dcn[t] = doc[j]; s_dmn[t] = dom[j];
        s_dgn[t] = dgen[j]; s_scn[t] = scr[j];
    }

    float acc[4][8] = {};
    const float4* N4 = (const float4*)g_norm;

    for (int kk = 0; kk < Esz; kk += 8) {
        if (t < 128) {
            int arow = t >> 1, ak = (t & 1) * 4;
            float4 a = N4[(m0 + arow) * 64 + ((kk + ak) >> 2)];
            As[ak + 0][arow] = a.x; As[ak + 1][arow] = a.y;
            As[ak + 2][arow] = a.z; As[ak + 3][arow] = a.w;
        }
        {
            int brow = t >> 1, bk = (t & 1) * 4;
            float4 b = N4[(n0 + brow) * 64 + ((kk + bk) >> 2)];
            Bs[bk + 0][brow] = b.x; Bs[bk + 1][brow] = b.y;
            Bs[bk + 2][brow] = b.z; Bs[bk + 3][brow] = b.w;
        }
        __syncthreads();
        #pragma unroll
        for (int k = 0; k < 8; k++) {
            float4 a  = *(const float4*)&As[k][ty * 4];
            float4 b0 = *(const float4*)&Bs[k][tx * 8];
            float4 b1 = *(const float4*)&Bs[k][tx * 8 + 4];
            float av[4] = {a.x, a.y, a.z, a.w};
            float bv[8] = {b0.x, b0.y, b0.z, b0.w, b1.x, b1.y, b1.z, b1.w};
            #pragma unroll
            for (int i = 0; i < 4; i++)
                #pragma unroll
                for (int j = 0; j < 8; j++)
                    acc[i][j] += av[i] * bv[j];
        }
        __syncthreads();
    }

    // Epilogue: per-row pos/neg exp sums over this 64x128 tile.
    #pragma unroll
    for (int ii = 0; ii < 4; ii++) {
        int rl = ty * 4 + ii;
        int iglob = m0 + rl;
        int li = s_lm[rl], idx = s_ixm[rl];
        int di = s_dcm[rl], dmi = s_dmm[rl], dgi = s_dgm[rl], si = s_scm[rl];
        float ps = 0.f, ns = 0.f;
        #pragma unroll
        for (int jj = 0; jj < 8; jj++) {
            int cl = tx * 8 + jj;
            int jglob = n0 + cl;
            float e = __expf(acc[ii][jj] * 10.0f);
            int lj = s_ln[cl];
            if (lj == li) {
                if (jglob != iglob) ps += e;
            } else {
                bool sc = (s_scn[cl] == si);
                bool dc = (s_dcn[cl] == di);
                bool dm = (s_dmn[cl] == dmi);
                bool dg = (s_dgn[cl] == dgi);
                bool neg;
                switch (idx) {
                    case 0: neg = sc && dc; break;
                    case 1: neg = sc && dm; break;
                    case 2: neg = sc && dg; break;
                    case 3: neg = sc; break;
                    case 4: neg = dc; break;
                    case 5: neg = dm; break;
                    case 6: neg = dg; break;
                    default: neg = true; break;
                }
                if (neg) ns += e;
            }
        }
        // reduce across the 16 tx lanes (lane bits 0..3 within warp)
        #pragma unroll
        for (int o = 8; o > 0; o >>= 1) {
            ps += __shfl_xor_sync(0xffffffffu, ps, o);
            ns += __shfl_xor_sync(0xffffffffu, ns, o);
        }
        if (tx == 0) {
            atomicAdd(&g_ps[iglob], ps);
            atomicAdd(&g_ns[iglob], ns);
        }
    }
}

// ---------------------------------------------------------------------------
// 5) Cross-entropy: single-pass online softmax per row.
// ---------------------------------------------------------------------------
__global__ void ce_kernel(const float* __restrict__ logits,
                          const int* __restrict__ labels) {
    int b = blockIdx.x;
    int t = threadIdx.x;
    const float* row = logits + (size_t)b * Csz;

    float m = -1e30f, s = 0.f;
    for (int c = t; c < Csz; c += 256) {
        float v = row[c];
        if (v > m) { s = s * __expf(m - v) + 1.f; m = v; }
        else        s += __expf(v - m);
    }
    __shared__ float sm[256], ss[256];
    sm[t] = m; ss[t] = s;
    __syncthreads();
    for (int st = 128; st > 0; st >>= 1) {
        if (t < st) {
            float m1 = sm[t], s1 = ss[t];
            float m2 = sm[t + st], s2 = ss[t + st];
            float M = fmaxf(m1, m2);
            sm[t] = M;
            ss[t] = s1 * __expf(m1 - M) + s2 * __expf(m2 - M);
        }
        __syncthreads();
    }
    if (t == 0) {
        float lse = sm[0] + logf(ss[0]);
        g_ce[b] = lse - row[labels[b]];
    }
}

// ---------------------------------------------------------------------------
// 6) Final scalar: loss = mean(ce) + sum(con)/cnt
// ---------------------------------------------------------------------------
__global__ void final_kernel(float* __restrict__ out) {
    int t = threadIdx.x;  // 1024
    float ps = g_ps[t], ns = g_ns[t];
    float con, hp;
    if (ps > 0.f) { con = -logf(ps / (ps + ns)); hp = 1.f; }
    else          { con = 0.f; hp = 0.f; }

    __shared__ float s_ce[1024], s_co[1024], s_hp[1024];
    s_ce[t] = g_ce[t];
    s_co[t] = con;
    s_hp[t] = hp;
    __syncthreads();
    for (int s = 512; s > 0; s >>= 1) {
        if (t < s) {
            s_ce[t] += s_ce[t + s];
            s_co[t] += s_co[t + s];
            s_hp[t] += s_hp[t + s];
        }
        __syncthreads();
    }
    if (t == 0) {
        float ce = s_ce[0] / (float)Bsz;
        float cnt = s_hp[0];
        float c = (cnt > 0.f) ? (s_co[0] / cnt) : 0.f;
        out[0] = ce + c;
    }
}

// ---------------------------------------------------------------------------
extern "C" void kernel_launch(void* const* d_in, const int* in_sizes, int n_in,
                              void* d_out, int out_size) {
    const int*   input_ids = (const int*)d_in[0];
    const int*   labels    = (const int*)d_in[1];
    const int*   doc_ids   = (const int*)d_in[2];
    const int*   dom_ids   = (const int*)d_in[3];
    const int*   dgen_ids  = (const int*)d_in[4];
    const int*   scr_ids   = (const int*)d_in[5];
    const float* emb_table = (const float*)d_in[6];
    const float* fc_w      = (const float*)d_in[7];
    const float* fc_b      = (const float*)d_in[8];

    float* out    = (float*)d_out;
    float* logits = out + 1;  // [loss, logits(B*C)]

    pool_kernel<<<Bsz / 4, 256>>>(input_ids, emb_table);
    negidx_kernel<<<Bsz, 256>>>(labels, doc_ids, dom_ids, dgen_ids, scr_ids);
    gemm_logits_kernel<<<dim3((Csz + 127) / 128, Bsz / 64), 256>>>(fc_w, fc_b, logits);
    sim_con_kernel<<<dim3(Bsz / 128, Bsz / 64), 256>>>(labels, doc_ids, dom_ids, dgen_ids, scr_ids);
    ce_kernel<<<Bsz, 256>>>(logits, labels);
    final_kernel<<<1, 1024>>>(out);
}

// round 4
// speedup vs baseline: 1.1045x; 1.1037x over previous
#include <cuda_runtime.h>
#include <math.h>

#define Bsz 1024
#define Lsz 256
#define Esz 256
#define Csz 2000
#define MIN_NEG 10
#define NTILES_C 16   // 16 n-tiles of 128 cover Csz=2000

// Scratch (__device__ globals: allocation-free rule)
__device__ float g_pooled[Bsz * Esz];
__device__ float g_norm[Bsz * Esz];
__device__ float g_ps[Bsz];
__device__ float g_ns[Bsz];
__device__ int   g_negidx[Bsz];
__device__ float g_cem[Bsz * NTILES_C];  // CE online-softmax partial max
__device__ float g_ces[Bsz * NTILES_C];  // CE online-softmax partial sum

// ---------------------------------------------------------------------------
// 1) Masked mean pooling + L2 normalize. 4 rows/block, 64 threads/row.
//    Valid ids are ballot-compacted into smem so the gather loop is
//    branch-free -> unroll-8 independent LDGs (high MLP).
// ---------------------------------------------------------------------------
__global__ void pool_kernel(const int* __restrict__ ids,
                            const float* __restrict__ emb) {
    int t = threadIdx.x;
    __shared__ int sid[4][256];
    __shared__ int scnt[4];
    if (t < 4) scnt[t] = 0;
    __syncthreads();

    #pragma unroll
    for (int i = 0; i < 4; i++) {
        int id = ids[blockIdx.x * 1024 + i * 256 + t];
        bool valid = (id > 1);  // id != UNK(0) && id != PAD(1)
        unsigned mask = __ballot_sync(0xffffffffu, valid);
        int base = 0;
        if ((t & 31) == 0) base = atomicAdd(&scnt[i], __popc(mask));
        base = __shfl_sync(0xffffffffu, base, 0);
        if (valid) {
            int pos = base + __popc(mask & ((1u << (t & 31)) - 1u));
            sid[i][pos] = id;
        }
    }
    __syncthreads();

    int sub = t >> 6;          // row within block
    int lane = t & 63;         // float4 column
    int b = blockIdx.x * 4 + sub;
    int cnt = scnt[sub];
    const int* myids = sid[sub];
    const float4* emb4 = (const float4*)emb;

    float4 acc = make_float4(0.f, 0.f, 0.f, 0.f);
    int l = 0;
    for (; l + 8 <= cnt; l += 8) {
        float4 v0 = emb4[(size_t)myids[l + 0] * 64 + lane];
        float4 v1 = emb4[(size_t)myids[l + 1] * 64 + lane];
        float4 v2 = emb4[(size_t)myids[l + 2] * 64 + lane];
        float4 v3 = emb4[(size_t)myids[l + 3] * 64 + lane];
        float4 v4 = emb4[(size_t)myids[l + 4] * 64 + lane];
        float4 v5 = emb4[(size_t)myids[l + 5] * 64 + lane];
        float4 v6 = emb4[(size_t)myids[l + 6] * 64 + lane];
        float4 v7 = emb4[(size_t)myids[l + 7] * 64 + lane];
        acc.x += v0.x + v1.x + v2.x + v3.x + v4.x + v5.x + v6.x + v7.x;
        acc.y += v0.y + v1.y + v2.y + v3.y + v4.y + v5.y + v6.y + v7.y;
        acc.z += v0.z + v1.z + v2.z + v3.z + v4.z + v5.z + v6.z + v7.z;
        acc.w += v0.w + v1.w + v2.w + v3.w + v4.w + v5.w + v6.w + v7.w;
    }
    for (; l < cnt; l++) {
        float4 v = emb4[(size_t)myids[l] * 64 + lane];
        acc.x += v.x; acc.y += v.y; acc.z += v.z; acc.w += v.w;
    }
    float ic = 1.0f / (float)cnt;
    float4 p = make_float4(acc.x * ic, acc.y * ic, acc.z * ic, acc.w * ic);

    __shared__ float sh[256];
    sh[t] = p.x * p.x + p.y * p.y + p.z * p.z + p.w * p.w;
    __syncthreads();
    for (int s = 32; s > 0; s >>= 1) {
        if (lane < s) sh[t] += sh[t + s];
        __syncthreads();
    }
    float inv = rsqrtf(sh[sub << 6]);

    ((float4*)g_pooled)[b * 64 + lane] = p;
    ((float4*)g_norm)[b * 64 + lane] =
        make_float4(p.x * inv, p.y * inv, p.z * inv, p.w * inv);
}

// ---------------------------------------------------------------------------
// 2) Negative-condition selection per row; zeroes g_ps/g_ns (runs before the
//    fused kernel in stream order).
// ---------------------------------------------------------------------------
__global__ void negidx_kernel(const int* __restrict__ lab,
                              const int* __restrict__ doc,
                              const int* __restrict__ dom,
                              const int* __restrict__ dgen,
                              const int* __restrict__ scr) {
    int i = blockIdx.x;
    int t = threadIdx.x;
    if (t == 0) { g_ps[i] = 0.f; g_ns[i] = 0.f; }
    int li = lab[i], di = doc[i], dmi = dom[i], dgi = dgen[i], si = scr[i];

    int c[8] = {0,0,0,0,0,0,0,0};
    for (int j = t; j < Bsz; j += 256) {
        if (lab[j] != li) {
            int sc = (scr[j] == si);
            int dc = (doc[j] == di);
            int dm = (dom[j] == dmi);
            int dg = (dgen[j] == dgi);
            c[0] += sc & dc; c[1] += sc & dm; c[2] += sc & dg; c[3] += sc;
            c[4] += dc;      c[5] += dm;      c[6] += dg;      c[7] += 1;
        }
    }
    __shared__ int tot[8];
    if (t < 8) tot[t] = 0;
    __syncthreads();
    #pragma unroll
    for (int k = 0; k < 8; k++)
        if (c[k]) atomicAdd(&tot[k], c[k]);
    __syncthreads();
    if (t == 0) {
        int idx = 7;
        #pragma unroll
        for (int k = 7; k >= 0; k--)
            if (tot[k] >= MIN_NEG) idx = k;
        g_negidx[i] = idx;
    }
}

// ---------------------------------------------------------------------------
// 3) ONE fused kernel, 384 blocks x 256 threads:
//      blocks [0,256):   logits tiles (64x128) + CE online-softmax partials
//      blocks [256,384): sim tiles (64x128) + contrastive exp-sum epilogue
//    Merging the two independent GEMMs into one launch raises blocks/SM from
//    ~1 to ~2.6 (latency hiding) and overlaps them on the chip.
// ---------------------------------------------------------------------------
__global__ void fused_mm_kernel(const float* __restrict__ W,
                                const float* __restrict__ bias,
                                float* __restrict__ logits,
                                const int* __restrict__ lab,
                                const int* __restrict__ doc,
                                const int* __restrict__ dom,
                                const int* __restrict__ dgen,
                                const int* __restrict__ scr) {
    __shared__ float As[8][64];
    __shared__ float Bs[8][128];
    __shared__ int s_lm[64], s_dcm[64], s_dmm[64], s_dgm[64], s_scm[64], s_ixm[64];
    __shared__ int s_ln[128], s_dcn[128], s_dmn[128], s_dgn[128], s_scn[128];

    int t = threadIdx.x;
    int tx = t & 15, ty = t >> 4;
    int blk = blockIdx.x;

    if (blk < 256) {
        // ---------------- logits path ----------------
        int nb = blk & 15, mb = blk >> 4;
        int n0 = nb * 128, m0 = mb * 64;
        float acc[4][8] = {};
        const float4* P4 = (const float4*)g_pooled;

        for (int kk = 0; kk < Esz; kk += 8) {
            if (t < 128) {
                int arow = t >> 1, ak = (t & 1) * 4;
                float4 a = P4[(m0 + arow) * 64 + ((kk + ak) >> 2)];
                As[ak + 0][arow] = a.x; As[ak + 1][arow] = a.y;
                As[ak + 2][arow] = a.z; As[ak + 3][arow] = a.w;
            }
            {
                int bk = t >> 5, bn = (t & 31) * 4;
                int col = n0 + bn;
                float4 bv = make_float4(0.f, 0.f, 0.f, 0.f);
                if (col < Csz)
                    bv = *(const float4*)&W[(size_t)(kk + bk) * Csz + col];
                *(float4*)&Bs[bk][bn] = bv;
            }
            __syncthreads();
            #pragma unroll
            for (int k = 0; k < 8; k++) {
                float4 a  = *(const float4*)&As[k][ty * 4];
                float4 b0 = *(const float4*)&Bs[k][tx * 8];
                float4 b1 = *(const float4*)&Bs[k][tx * 8 + 4];
                float av[4] = {a.x, a.y, a.z, a.w};
                float bv[8] = {b0.x, b0.y, b0.z, b0.w, b1.x, b1.y, b1.z, b1.w};
                #pragma unroll
                for (int i = 0; i < 4; i++)
                    #pragma unroll
                    for (int j = 0; j < 8; j++)
                        acc[i][j] += av[i] * bv[j];
            }
            __syncthreads();
        }

        float bb[8];
        #pragma unroll
        for (int j = 0; j < 8; j++) {
            int col = n0 + tx * 8 + j;
            bb[j] = (col < Csz) ? bias[col] : 0.f;
        }
        #pragma unroll
        for (int i = 0; i < 4; i++) {
            int row = m0 + ty * 4 + i;
            // per-thread online softmax over this thread's 8 cols
            float m = -1e30f, s = 0.f;
            #pragma unroll
            for (int j = 0; j < 8; j++) {
                int col = n0 + tx * 8 + j;
                if (col < Csz) {
                    float v = acc[i][j] + bb[j];
                    logits[(size_t)row * Csz + col] = v;
                    if (v > m) { s = s * __expf(m - v) + 1.f; m = v; }
                    else         s += __expf(v - m);
                }
            }
            // merge across the 16 tx lanes
            #pragma unroll
            for (int o = 8; o > 0; o >>= 1) {
                float mo = __shfl_xor_sync(0xffffffffu, m, o);
                float so = __shfl_xor_sync(0xffffffffu, s, o);
                float M = fmaxf(m, mo);
                s = s * __expf(m - M) + so * __expf(mo - M);
                m = M;
            }
            if (tx == 0) {
                g_cem[row * NTILES_C + nb] = m;
                g_ces[row * NTILES_C + nb] = s;
            }
        }
    } else {
        // ---------------- sim + contrastive path ----------------
        int sblk = blk - 256;
        int nb = sblk & 7, mb = sblk >> 3;
        int n0 = nb * 128, m0 = mb * 64;

        if (t < 64) {
            int i = m0 + t;
            s_lm[t] = lab[i]; s_dcm[t] = doc[i]; s_dmm[t] = dom[i];
            s_dgm[t] = dgen[i]; s_scm[t] = scr[i]; s_ixm[t] = g_negidx[i];
        }
        if (t < 128) {
            int j = n0 + t;
            s_ln[t] = lab[j]; s_dcn[t] = doc[j]; s_dmn[t] = dom[j];
            s_dgn[t] = dgen[j]; s_scn[t] = scr[j];
        }

        float acc[4][8] = {};
        const float4* N4 = (const float4*)g_norm;

        for (int kk = 0; kk < Esz; kk += 8) {
            if (t < 128) {
                int arow = t >> 1, ak = (t & 1) * 4;
                float4 a = N4[(m0 + arow) * 64 + ((kk + ak) >> 2)];
                As[ak + 0][arow] = a.x; As[ak + 1][arow] = a.y;
                As[ak + 2][arow] = a.z; As[ak + 3][arow] = a.w;
            }
            {
                int brow = t >> 1, bk = (t & 1) * 4;
                float4 b = N4[(n0 + brow) * 64 + ((kk + bk) >> 2)];
                Bs[bk + 0][brow] = b.x; Bs[bk + 1][brow] = b.y;
                Bs[bk + 2][brow] = b.z; Bs[bk + 3][brow] = b.w;
            }
            __syncthreads();
            #pragma unroll
            for (int k = 0; k < 8; k++) {
                float4 a  = *(const float4*)&As[k][ty * 4];
                float4 b0 = *(const float4*)&Bs[k][tx * 8];
                float4 b1 = *(const float4*)&Bs[k][tx * 8 + 4];
                float av[4] = {a.x, a.y, a.z, a.w};
                float bv[8] = {b0.x, b0.y, b0.z, b0.w, b1.x, b1.y, b1.z, b1.w};
                #pragma unroll
                for (int i = 0; i < 4; i++)
                    #pragma unroll
                    for (int j = 0; j < 8; j++)
                        acc[i][j] += av[i] * bv[j];
            }
            __syncthreads();
        }

        #pragma unroll
        for (int ii = 0; ii < 4; ii++) {
            int rl = ty * 4 + ii;
            int iglob = m0 + rl;
            int li = s_lm[rl], idx = s_ixm[rl];
            int di = s_dcm[rl], dmi = s_dmm[rl], dgi = s_dgm[rl], si = s_scm[rl];
            float ps = 0.f, ns = 0.f;
            #pragma unroll
            for (int jj = 0; jj < 8; jj++) {
                int cl = tx * 8 + jj;
                int jglob = n0 + cl;
                float e = __expf(acc[ii][jj] * 10.0f);
                int lj = s_ln[cl];
                if (lj == li) {
                    if (jglob != iglob) ps += e;
                } else {
                    bool sc = (s_scn[cl] == si);
                    bool dc = (s_dcn[cl] == di);
                    bool dm = (s_dmn[cl] == dmi);
                    bool dg = (s_dgn[cl] == dgi);
                    bool neg;
                    switch (idx) {
                        case 0: neg = sc && dc; break;
                        case 1: neg = sc && dm; break;
                        case 2: neg = sc && dg; break;
                        case 3: neg = sc; break;
                        case 4: neg = dc; break;
                        case 5: neg = dm; break;
                        case 6: neg = dg; break;
                        default: neg = true; break;
                    }
                    if (neg) ns += e;
                }
            }
            #pragma unroll
            for (int o = 8; o > 0; o >>= 1) {
                ps += __shfl_xor_sync(0xffffffffu, ps, o);
                ns += __shfl_xor_sync(0xffffffffu, ns, o);
            }
            if (tx == 0) {
                atomicAdd(&g_ps[iglob], ps);
                atomicAdd(&g_ns[iglob], ns);
            }
        }
    }
}

// ---------------------------------------------------------------------------
// 4) Final: merge CE partials per row, gather label logit, combine losses.
// ---------------------------------------------------------------------------
__global__ void final_kernel(const float* __restrict__ logits,
                             const int* __restrict__ labels,
                             float* __restrict__ out) {
    int t = threadIdx.x;  // 1024 threads, one per row

    // CE: merge 16 online-softmax partials
    float m = -1e30f, s = 0.f;
    #pragma unroll
    for (int nb = 0; nb < NTILES_C; nb++) {
        float m2 = g_cem[t * NTILES_C + nb];
        float s2 = g_ces[t * NTILES_C + nb];
        float M = fmaxf(m, m2);
        s = s * __expf(m - M) + s2 * __expf(m2 - M);
        m = M;
    }
    float lse = m + logf(s);
    float ce = lse - logits[(size_t)t * Csz + labels[t]];

    // contrastive per-row
    float ps = g_ps[t], ns = g_ns[t];
    float con, hp;
    if (ps > 0.f) { con = -logf(ps / (ps + ns)); hp = 1.f; }
    else          { con = 0.f; hp = 0.f; }

    __shared__ float s_ce[1024], s_co[1024], s_hp[1024];
    s_ce[t] = ce;
    s_co[t] = con;
    s_hp[t] = hp;
    __syncthreads();
    for (int st = 512; st > 0; st >>= 1) {
        if (t < st) {
            s_ce[t] += s_ce[t + st];
            s_co[t] += s_co[t + st];
            s_hp[t] += s_hp[t + st];
        }
        __syncthreads();
    }
    if (t == 0) {
        float cem = s_ce[0] / (float)Bsz;
        float cnt = s_hp[0];
        float c = (cnt > 0.f) ? (s_co[0] / cnt) : 0.f;
        out[0] = cem + c;
    }
}

// ---------------------------------------------------------------------------
extern "C" void kernel_launch(void* const* d_in, const int* in_sizes, int n_in,
                              void* d_out, int out_size) {
    const int*   input_ids = (const int*)d_in[0];
    const int*   labels    = (const int*)d_in[1];
    const int*   doc_ids   = (const int*)d_in[2];
    const int*   dom_ids   = (const int*)d_in[3];
    const int*   dgen_ids  = (const int*)d_in[4];
    const int*   scr_ids   = (const int*)d_in[5];
    const float* emb_table = (const float*)d_in[6];
    const float* fc_w      = (const float*)d_in[7];
    const float* fc_b      = (const float*)d_in[8];

    float* out    = (float*)d_out;
    float* logits = out + 1;  // [loss, logits(B*C)]

    negidx_kernel<<<Bsz, 256>>>(labels, doc_ids, dom_ids, dgen_ids, scr_ids);
    pool_kernel<<<Bsz / 4, 256>>>(input_ids, emb_table);
    fused_mm_kernel<<<384, 256>>>(fc_w, fc_b, logits,
                                  labels, doc_ids, dom_ids, dgen_ids, scr_ids);
    final_kernel<<<1, 1024>>>(logits, labels, out);
}

// round 5
// speedup vs baseline: 1.1512x; 1.0423x over previous
#include <cuda_runtime.h>
#include <math.h>

#define Bsz 1024
#define Lsz 256
#define Esz 256
#define Csz 2000
#define MIN_NEG 10
#define NTILES_C 16   // 16 n-tiles of 128 cover Csz=2000

// Scratch (__device__ globals: allocation-free rule)
__device__ float g_pooled[Bsz * Esz];
__device__ float g_norm[Bsz * Esz];
__device__ float g_ps[Bsz];
__device__ float g_ns[Bsz];
__device__ int   g_negidx[Bsz];
__device__ float g_cem[Bsz * NTILES_C];  // CE online-softmax partial max
__device__ float g_ces[Bsz * NTILES_C];  // CE online-softmax partial sum
__device__ float g_acc[3];               // ce_sum, con_sum, has_pos_cnt

// ---------------------------------------------------------------------------
// 1) Masked mean pooling + L2 normalize. 4 rows/block, 64 threads/row.
//    Valid ids ballot-compacted into smem -> branch-free unroll-8 gather.
// ---------------------------------------------------------------------------
__global__ void pool_kernel(const int* __restrict__ ids,
                            const float* __restrict__ emb) {
    int t = threadIdx.x;
    __shared__ int sid[4][256];
    __shared__ int scnt[4];
    if (t < 4) scnt[t] = 0;
    __syncthreads();

    #pragma unroll
    for (int i = 0; i < 4; i++) {
        int id = ids[blockIdx.x * 1024 + i * 256 + t];
        bool valid = (id > 1);  // id != UNK(0) && id != PAD(1)
        unsigned mask = __ballot_sync(0xffffffffu, valid);
        int base = 0;
        if ((t & 31) == 0) base = atomicAdd(&scnt[i], __popc(mask));
        base = __shfl_sync(0xffffffffu, base, 0);
        if (valid) {
            int pos = base + __popc(mask & ((1u << (t & 31)) - 1u));
            sid[i][pos] = id;
        }
    }
    __syncthreads();

    int sub = t >> 6;
    int lane = t & 63;
    int b = blockIdx.x * 4 + sub;
    int cnt = scnt[sub];
    const int* myids = sid[sub];
    const float4* emb4 = (const float4*)emb;

    float4 acc = make_float4(0.f, 0.f, 0.f, 0.f);
    int l = 0;
    for (; l + 8 <= cnt; l += 8) {
        float4 v0 = emb4[(size_t)myids[l + 0] * 64 + lane];
        float4 v1 = emb4[(size_t)myids[l + 1] * 64 + lane];
        float4 v2 = emb4[(size_t)myids[l + 2] * 64 + lane];
        float4 v3 = emb4[(size_t)myids[l + 3] * 64 + lane];
        float4 v4 = emb4[(size_t)myids[l + 4] * 64 + lane];
        float4 v5 = emb4[(size_t)myids[l + 5] * 64 + lane];
        float4 v6 = emb4[(size_t)myids[l + 6] * 64 + lane];
        float4 v7 = emb4[(size_t)myids[l + 7] * 64 + lane];
        acc.x += v0.x + v1.x + v2.x + v3.x + v4.x + v5.x + v6.x + v7.x;
        acc.y += v0.y + v1.y + v2.y + v3.y + v4.y + v5.y + v6.y + v7.y;
        acc.z += v0.z + v1.z + v2.z + v3.z + v4.z + v5.z + v6.z + v7.z;
        acc.w += v0.w + v1.w + v2.w + v3.w + v4.w + v5.w + v6.w + v7.w;
    }
    for (; l < cnt; l++) {
        float4 v = emb4[(size_t)myids[l] * 64 + lane];
        acc.x += v.x; acc.y += v.y; acc.z += v.z; acc.w += v.w;
    }
    float ic = 1.0f / (float)cnt;
    float4 p = make_float4(acc.x * ic, acc.y * ic, acc.z * ic, acc.w * ic);

    __shared__ float sh[256];
    sh[t] = p.x * p.x + p.y * p.y + p.z * p.z + p.w * p.w;
    __syncthreads();
    for (int s = 32; s > 0; s >>= 1) {
        if (lane < s) sh[t] += sh[t + s];
        __syncthreads();
    }
    float inv = rsqrtf(sh[sub << 6]);

    ((float4*)g_pooled)[b * 64 + lane] = p;
    ((float4*)g_norm)[b * 64 + lane] =
        make_float4(p.x * inv, p.y * inv, p.z * inv, p.w * inv);
}

// ---------------------------------------------------------------------------
// 2) Negative-condition selection: 32 blocks x 256 threads, attributes staged
//    in smem, 8 threads per row. Also zeroes g_ps/g_ns and g_acc.
// ---------------------------------------------------------------------------
__global__ void negidx_kernel(const int* __restrict__ lab,
                              const int* __restrict__ doc,
                              const int* __restrict__ dom,
                              const int* __restrict__ dgen,
                              const int* __restrict__ scr) {
    __shared__ int sl[Bsz], sdc[Bsz], sdm[Bsz], sdg[Bsz], ssc[Bsz];
    int t = threadIdx.x;
    if (blockIdx.x == 0 && t < 3) g_acc[t] = 0.f;

    for (int idx = t; idx < Bsz; idx += 256) {
        sl[idx]  = lab[idx];
        sdc[idx] = doc[idx];
        sdm[idx] = dom[idx];
        sdg[idx] = dgen[idx];
        ssc[idx] = scr[idx];
    }
    __syncthreads();

    int r = blockIdx.x * 32 + (t >> 3);  // row
    int sub = t & 7;                     // 8 threads per row
    int li = sl[r], di = sdc[r], dmi = sdm[r], dgi = sdg[r], si = ssc[r];

    int c[8] = {0,0,0,0,0,0,0,0};
    #pragma unroll 4
    for (int j = sub; j < Bsz; j += 8) {
        if (sl[j] != li) {
            int sc = (ssc[j] == si);
            int dc = (sdc[j] == di);
            int dm = (sdm[j] == dmi);
            int dg = (sdg[j] == dgi);
            c[0] += sc & dc; c[1] += sc & dm; c[2] += sc & dg; c[3] += sc;
            c[4] += dc;      c[5] += dm;      c[6] += dg;      c[7] += 1;
        }
    }
    // reduce across the 8 sub-lanes (lanes of same row are adjacent in warp)
    #pragma unroll
    for (int o = 4; o > 0; o >>= 1)
        #pragma unroll
        for (int k = 0; k < 8; k++)
            c[k] += __shfl_xor_sync(0xffffffffu, c[k], o);

    if (sub == 0) {
        int idx = 7;
        #pragma unroll
        for (int k = 7; k >= 0; k--)
            if (c[k] >= MIN_NEG) idx = k;
        g_negidx[r] = idx;
        g_ps[r] = 0.f;
        g_ns[r] = 0.f;
    }
}

// ---------------------------------------------------------------------------
// 3) Fused GEMM kernel, 384 blocks x 256 threads, BK=16, register prefetch:
//      blocks [0,256):   logits tiles (64x128) + CE online-softmax partials
//      blocks [256,384): sim tiles (64x128) + contrastive epilogue
// ---------------------------------------------------------------------------
__global__ void __launch_bounds__(256)
fused_mm_kernel(const float* __restrict__ W,
                const float* __restrict__ bias,
                float* __restrict__ logits,
                const int* __restrict__ lab,
                const int* __restrict__ doc,
                const int* __restrict__ dom,
                const int* __restrict__ dgen,
                const int* __restrict__ scr) {
    __shared__ float As[16][64];
    __shared__ float Bs[16][128];
    __shared__ int s_lm[64], s_dcm[64], s_dmm[64], s_dgm[64], s_scm[64], s_ixm[64];
    __shared__ int s_ln[128], s_dcn[128], s_dmn[128], s_dgn[128], s_scn[128];

    int t = threadIdx.x;
    int tx = t & 15, ty = t >> 4;
    int blk = blockIdx.x;
    float acc[4][8] = {};

    if (blk < 256) {
        // ---------------- logits path ----------------
        int nb = blk & 15, mb = blk >> 4;
        int n0 = nb * 128, m0 = mb * 64;
        const float4* P4 = (const float4*)g_pooled;

        // A: thread t loads row t>>2, k-chunk (t&3)*4.  B: 2 float4 per thread.
        int arow = t >> 2, ak = (t & 3) * 4;
        int bk0 = t >> 5,        bn0 = (t & 31) * 4;
        int bk1 = (t + 256) >> 5, bn1 = bn0;

        float4 ra = P4[(m0 + arow) * 64 + (ak >> 2)];
        float4 rb0 = make_float4(0.f,0.f,0.f,0.f), rb1 = rb0;
        if (n0 + bn0 < Csz) {
            rb0 = *(const float4*)&W[(size_t)bk0 * Csz + n0 + bn0];
            rb1 = *(const float4*)&W[(size_t)bk1 * Csz + n0 + bn1];
        }

        for (int kk = 0; kk < Esz; kk += 16) {
            __syncthreads();
            As[ak + 0][arow] = ra.x; As[ak + 1][arow] = ra.y;
            As[ak + 2][arow] = ra.z; As[ak + 3][arow] = ra.w;
            *(float4*)&Bs[bk0][bn0] = rb0;
            *(float4*)&Bs[bk1][bn1] = rb1;
            __syncthreads();

            int nk = kk + 16;
            if (nk < Esz) {
                ra = P4[(m0 + arow) * 64 + ((nk + ak) >> 2)];
                if (n0 + bn0 < Csz) {
                    rb0 = *(const float4*)&W[(size_t)(nk + bk0) * Csz + n0 + bn0];
                    rb1 = *(const float4*)&W[(size_t)(nk + bk1) * Csz + n0 + bn1];
                }
            }
            #pragma unroll
            for (int k = 0; k < 16; k++) {
                float4 a  = *(const float4*)&As[k][ty * 4];
                float4 b0 = *(const float4*)&Bs[k][tx * 8];
                float4 b1 = *(const float4*)&Bs[k][tx * 8 + 4];
                float av[4] = {a.x, a.y, a.z, a.w};
                float bv[8] = {b0.x, b0.y, b0.z, b0.w, b1.x, b1.y, b1.z, b1.w};
                #pragma unroll
                for (int i = 0; i < 4; i++)
                    #pragma unroll
                    for (int j = 0; j < 8; j++)
                        acc[i][j] += av[i] * bv[j];
            }
        }

        float bb[8];
        #pragma unroll
        for (int j = 0; j < 8; j++) {
            int col = n0 + tx * 8 + j;
            bb[j] = (col < Csz) ? bias[col] : 0.f;
        }
        #pragma unroll
        for (int i = 0; i < 4; i++) {
            int row = m0 + ty * 4 + i;
            float m = -1e30f, s = 0.f;
            #pragma unroll
            for (int j = 0; j < 8; j++) {
                int col = n0 + tx * 8 + j;
                if (col < Csz) {
                    float v = acc[i][j] + bb[j];
                    logits[(size_t)row * Csz + col] = v;
                    if (v > m) { s = s * __expf(m - v) + 1.f; m = v; }
                    else         s += __expf(v - m);
                }
            }
            #pragma unroll
            for (int o = 8; o > 0; o >>= 1) {
                float mo = __shfl_xor_sync(0xffffffffu, m, o);
                float so = __shfl_xor_sync(0xffffffffu, s, o);
                float M = fmaxf(m, mo);
                s = s * __expf(m - M) + so * __expf(mo - M);
                m = M;
            }
            if (tx == 0) {
                g_cem[row * NTILES_C + nb] = m;
                g_ces[row * NTILES_C + nb] = s;
            }
        }
    } else {
        // ---------------- sim + contrastive path ----------------
        int sblk = blk - 256;
        int nb = sblk & 7, mb = sblk >> 3;
        int n0 = nb * 128, m0 = mb * 64;

        if (t < 64) {
            int i = m0 + t;
            s_lm[t] = lab[i]; s_dcm[t] = doc[i]; s_dmm[t] = dom[i];
            s_dgm[t] = dgen[i]; s_scm[t] = scr[i]; s_ixm[t] = g_negidx[i];
        }
        if (t < 128) {
            int j = n0 + t;
            s_ln[t] = lab[j]; s_dcn[t] = doc[j]; s_dmn[t] = dom[j];
            s_dgn[t] = dgen[j]; s_scn[t] = scr[j];
        }

        const float4* N4 = (const float4*)g_norm;
        int arow = t >> 2, ak = (t & 3) * 4;            // A: 64x16
        int brow0 = t >> 1, bk0 = (t & 1) * 8;          // B: 128x16, 2 float4/thread
        // thread loads B[brow0][bk0..bk0+3] and B[brow0][bk0+4..bk0+7]

        float4 ra = N4[(m0 + arow) * 64 + (ak >> 2)];
        float4 rb0 = N4[(n0 + brow0) * 64 + (bk0 >> 2)];
        float4 rb1 = N4[(n0 + brow0) * 64 + (bk0 >> 2) + 1];

        for (int kk = 0; kk < Esz; kk += 16) {
            __syncthreads();
            As[ak + 0][arow] = ra.x; As[ak + 1][arow] = ra.y;
            As[ak + 2][arow] = ra.z; As[ak + 3][arow] = ra.w;
            Bs[bk0 + 0][brow0] = rb0.x; Bs[bk0 + 1][brow0] = rb0.y;
            Bs[bk0 + 2][brow0] = rb0.z; Bs[bk0 + 3][brow0] = rb0.w;
            Bs[bk0 + 4][brow0] = rb1.x; Bs[bk0 + 5][brow0] = rb1.y;
            Bs[bk0 + 6][brow0] = rb1.z; Bs[bk0 + 7][brow0] = rb1.w;
            __syncthreads();

            int nk = kk + 16;
            if (nk < Esz) {
                ra  = N4[(m0 + arow) * 64 + ((nk + ak) >> 2)];
                rb0 = N4[(n0 + brow0) * 64 + ((nk + bk0) >> 2)];
                rb1 = N4[(n0 + brow0) * 64 + ((nk + bk0) >> 2) + 1];
            }
            #pragma unroll
            for (int k = 0; k < 16; k++) {
                float4 a  = *(const float4*)&As[k][ty * 4];
                float4 b0 = *(const float4*)&Bs[k][tx * 8];
                float4 b1 = *(const float4*)&Bs[k][tx * 8 + 4];
                float av[4] = {a.x, a.y, a.z, a.w};
                float bv[8] = {b0.x, b0.y, b0.z, b0.w, b1.x, b1.y, b1.z, b1.w};
                #pragma unroll
                for (int i = 0; i < 4; i++)
                    #pragma unroll
                    for (int j = 0; j < 8; j++)
                        acc[i][j] += av[i] * bv[j];
            }
        }

        #pragma unroll
        for (int ii = 0; ii < 4; ii++) {
            int rl = ty * 4 + ii;
            int iglob = m0 + rl;
            int li = s_lm[rl], idx = s_ixm[rl];
            int di = s_dcm[rl], dmi = s_dmm[rl], dgi = s_dgm[rl], si = s_scm[rl];
            float ps = 0.f, ns = 0.f;
            #pragma unroll
            for (int jj = 0; jj < 8; jj++) {
                int cl = tx * 8 + jj;
                int jglob = n0 + cl;
                float e = __expf(acc[ii][jj] * 10.0f);
                int lj = s_ln[cl];
                if (lj == li) {
                    if (jglob != iglob) ps += e;
                } else {
                    bool sc = (s_scn[cl] == si);
                    bool dc = (s_dcn[cl] == di);
                    bool dm = (s_dmn[cl] == dmi);
                    bool dg = (s_dgn[cl] == dgi);
                    bool neg;
                    switch (idx) {
                        case 0: neg = sc && dc; break;
                        case 1: neg = sc && dm; break;
                        case 2: neg = sc && dg; break;
                        case 3: neg = sc; break;
                        case 4: neg = dc; break;
                        case 5: neg = dm; break;
                        case 6: neg = dg; break;
                        default: neg = true; break;
                    }
                    if (neg) ns += e;
                }
            }
            #pragma unroll
            for (int o = 8; o > 0; o >>= 1) {
                ps += __shfl_xor_sync(0xffffffffu, ps, o);
                ns += __shfl_xor_sync(0xffffffffu, ns, o);
            }
            if (tx == 0) {
                atomicAdd(&g_ps[iglob], ps);
                atomicAdd(&g_ns[iglob], ns);
            }
        }
    }
}

// ---------------------------------------------------------------------------
// 4a) Per-row finalize: 16 blocks x 64 threads (one thread per row).
// ---------------------------------------------------------------------------
__global__ void row_kernel(const float* __restrict__ logits,
                           const int* __restrict__ labels) {
    int t = threadIdx.x;
    int r = blockIdx.x * 64 + t;

    float m = -1e30f, s = 0.f;
    #pragma unroll
    for (int nb = 0; nb < NTILES_C; nb++) {
        float m2 = g_cem[r * NTILES_C + nb];
        float s2 = g_ces[r * NTILES_C + nb];
        float M = fmaxf(m, m2);
        s = s * __expf(m - M) + s2 * __expf(m2 - M);
        m = M;
    }
    float ce = m + logf(s) - logits[(size_t)r * Csz + labels[r]];

    float ps = g_ps[r], ns = g_ns[r];
    float con, hp;
    if (ps > 0.f) { con = -logf(ps / (ps + ns)); hp = 1.f; }
    else          { con = 0.f; hp = 0.f; }

    // warp reduce (2 warps of 32) then smem combine
    #pragma unroll
    for (int o = 16; o > 0; o >>= 1) {
        ce  += __shfl_xor_sync(0xffffffffu, ce,  o);
        con += __shfl_xor_sync(0xffffffffu, con, o);
        hp  += __shfl_xor_sync(0xffffffffu, hp,  o);
    }
    __shared__ float w0[3], w1[3];
    if ((t & 31) == 0) {
        float* w = (t < 32) ? w0 : w1;
        w[0] = ce; w[1] = con; w[2] = hp;
    }
    __syncthreads();
    if (t == 0) {
        atomicAdd(&g_acc[0], w0[0] + w1[0]);
        atomicAdd(&g_acc[1], w0[1] + w1[1]);
        atomicAdd(&g_acc[2], w0[2] + w1[2]);
    }
}

// 4b) Scalar write.
__global__ void write_kernel(float* __restrict__ out) {
    float ce = g_acc[0] / (float)Bsz;
    float cnt = g_acc[2];
    float con = (cnt > 0.f) ? (g_acc[1] / cnt) : 0.f;
    out[0] = ce + con;
}

// ---------------------------------------------------------------------------
extern "C" void kernel_launch(void* const* d_in, const int* in_sizes, int n_in,
                              void* d_out, int out_size) {
    const int*   input_ids = (const int*)d_in[0];
    const int*   labels    = (const int*)d_in[1];
    const int*   doc_ids   = (const int*)d_in[2];
    const int*   dom_ids   = (const int*)d_in[3];
    const int*   dgen_ids  = (const int*)d_in[4];
    const int*   scr_ids   = (const int*)d_in[5];
    const float* emb_table = (const float*)d_in[6];
    const float* fc_w      = (const float*)d_in[7];
    const float* fc_b      = (const float*)d_in[8];

    float* out    = (float*)d_out;
    float* logits = out + 1;  // [loss, logits(B*C)]

    negidx_kernel<<<32, 256>>>(labels, doc_ids, dom_ids, dgen_ids, scr_ids);
    pool_kernel<<<Bsz / 4, 256>>>(input_ids, emb_table);
    fused_mm_kernel<<<384, 256>>>(fc_w, fc_b, logits,
                                  labels, doc_ids, dom_ids, dgen_ids, scr_ids);
    row_kernel<<<16, 64>>>(logits, labels);
    write_kernel<<<1, 1>>>(out);
}